// round 13
// baseline (speedup 1.0000x reference)
#include <cuda_runtime.h>
#include <cuda_bf16.h>
#include <cuda_fp16.h>
#include <math.h>

#define NN 10000
#define EE 640000
#define DD 128
#define BUCKET 192
#define KP 136   // padded k stride (bf16 elems)

// ---------------- device scratch ----------------
__device__ float g_y[NN * DD];        // fp8-packed message table
__device__ float g_aggr[NN * DD];
__device__ float g_h0[NN * DD];
__device__ float g_h1[NN * DD];
__device__ int   g_fill[NN];
__device__ int   g_colb[NN * BUCKET];
// transposed bf16 weights: lin0 @0 | agg0 ch0 @16384 ch1 @32768 | lin1 @49152 | agg1 ch0 @65536 ch1 @81920
__device__ __nv_bfloat16 g_wt[16384 * 6];
__device__ float g_wc[128 * 64];      // combined mp_w1 @ mp_w2
__device__ float g_bc[64];            // combined mp_b1 @ mp_w2 + mp_b2

// ---------------- adjacency fill: 8 edges/thread (embedded dtype sniff) ----------------
__global__ void __launch_bounds__(256) fill_k(const void* __restrict__ ei) {
    __shared__ int s64;
    if (threadIdx.x == 0) {
        const int* w = (const int*)ei;
        int ornz = 0;
#pragma unroll
        for (int j = 1; j < 64; j += 2) ornz |= w[j];
        s64 = (ornz == 0);
    }
    __syncthreads();
    int base0 = (blockIdx.x * 256 + threadIdx.x) * 8;
#pragma unroll
    for (int half = 0; half < 2; half++) {
        int base = base0 + half * 4;
        if (base >= EE) break;
        int d[4], s[4];
        if (s64) {
            const longlong2* pd = (const longlong2*)((const long long*)ei + EE + base);
            const longlong2* ps = (const longlong2*)((const long long*)ei + base);
            longlong2 q0 = pd[0], q1 = pd[1];
            longlong2 r0 = ps[0], r1 = ps[1];
            d[0] = (int)q0.x; d[1] = (int)q0.y; d[2] = (int)q1.x; d[3] = (int)q1.y;
            s[0] = (int)r0.x; s[1] = (int)r0.y; s[2] = (int)r1.x; s[3] = (int)r1.y;
        } else {
            int4 q = *(const int4*)((const int*)ei + EE + base);
            int4 r = *(const int4*)((const int*)ei + base);
            d[0] = q.x; d[1] = q.y; d[2] = q.z; d[3] = q.w;
            s[0] = r.x; s[1] = r.y; s[2] = r.z; s[3] = r.w;
        }
#pragma unroll
        for (int i = 0; i < 4; i++) {
            int pos = atomicAdd(&g_fill[d[i]], 1);
            if (pos < BUCKET) g_colb[d[i] * BUCKET + pos] = s[i];
        }
    }
}

// ---------------- weight prep ----------------
__global__ void __launch_bounds__(256) prep_k(
    const float* __restrict__ w0, const float* __restrict__ aw0,
    const float* __restrict__ w1, const float* __restrict__ aw1,
    const float* __restrict__ mw1, const float* __restrict__ mb1,
    const float* __restrict__ mw2, const float* __restrict__ mb2)
{
    int idx = blockIdx.x * 256 + threadIdx.x;   // 0..32767
    if (idx < 24576) {
        const float* src; int dstb, f;
        if (idx < 4096)       { src = w0;  dstb = 0;     f = idx; }
        else if (idx < 12288) { src = aw0; dstb = 16384; f = idx - 4096; }
        else if (idx < 16384) { src = w1;  dstb = 49152; f = idx - 12288; }
        else                  { src = aw1; dstb = 65536; f = idx - 16384; }
        float4 v = ((const float4*)src)[f];
        int k  = f >> 5;
        int n0 = (f & 31) * 4;
        int ch = k >> 7, kk = k & 127;
        __nv_bfloat16* dst = g_wt + dstb + ch * 16384 + kk;
        dst[(n0 + 0) * 128] = __float2bfloat16_rn(v.x);
        dst[(n0 + 1) * 128] = __float2bfloat16_rn(v.y);
        dst[(n0 + 2) * 128] = __float2bfloat16_rn(v.z);
        dst[(n0 + 3) * 128] = __float2bfloat16_rn(v.w);
    } else {
        int j = idx - 24576;                // 0..8191
        int m = j >> 6, n = j & 63;
        float s = 0.f;
#pragma unroll 8
        for (int k = 0; k < 128; k++)
            s += mw1[m * 128 + k] * mw2[k * 64 + n];
        g_wc[j] = s;
        if (j < 64) {
            float t = mb2[j];
#pragma unroll 8
            for (int k = 0; k < 128; k++)
                t += mb1[k] * mw2[k * 64 + j];
            g_bc[j] = t;
        }
    }
}

// ---------------- fp8 helpers ----------------
__device__ __forceinline__ unsigned short pack_e4m3x2(float v0, float v1) {
    unsigned short r;
    asm("cvt.rn.satfinite.e4m3x2.f32 %0, %2, %1;" : "=h"(r) : "f"(v0), "f"(v1));
    return r;
}
__device__ __forceinline__ void e4m3x4_to_h2(unsigned v, unsigned& h01, unsigned& h23) {
    asm("{ .reg .b16 lo, hi;\n\t"
        "mov.b32 {lo, hi}, %2;\n\t"
        "cvt.rn.f16x2.e4m3x2 %0, lo;\n\t"
        "cvt.rn.f16x2.e4m3x2 %1, hi; }"
        : "=r"(h01), "=r"(h23) : "r"(v));
}

// ---------------- GEMM building blocks (M=16 tiles) ----------------
// 256 thr = 8 warps, each warp: all 16 rows x 16 cols (warpN = wid).
__device__ __forceinline__ void stage_w(__nv_bfloat16* ws, const __nv_bfloat16* Wsrc, int tid) {
    const uint4* Wg = (const uint4*)Wsrc;
#pragma unroll
    for (int it = 0; it < 8; it++) {
        int idx = tid + it * 256;
        int n = idx >> 4, k8 = idx & 15;
        *(uint4*)(ws + n * KP + k8 * 8) = Wg[idx];
    }
}
__device__ __forceinline__ void stage_x16(__nv_bfloat16* xs, const float* Asrc, int row0, int tid) {
#pragma unroll
    for (int it = 0; it < 2; it++) {
        int idx = tid + it * 256;      // 512 = 16 rows x 32 float4
        int r = idx >> 5, c4 = idx & 31;
        int row = row0 + r;
        float4 v = make_float4(0.f, 0.f, 0.f, 0.f);
        if (row < NN) v = ((const float4*)Asrc)[row * 32 + c4];
        __nv_bfloat162 p0 = __floats2bfloat162_rn(v.x, v.y);
        __nv_bfloat162 p1 = __floats2bfloat162_rn(v.z, v.w);
        *(uint2*)(xs + r * KP + c4 * 4) = make_uint2(*(unsigned*)&p0, *(unsigned*)&p1);
    }
}
__device__ __forceinline__ void mma_tile16(const __nv_bfloat16* ws, const __nv_bfloat16* xs,
                                           int warpN, int gid, int tig,
                                           float acc[2][4]) {
#pragma unroll
    for (int ks = 0; ks < 8; ks++) {
        const int k0 = ks * 16;
        const __nv_bfloat16* xr0 = xs + gid * KP + k0 + 2 * tig;
        const __nv_bfloat16* xr1 = xr0 + 8 * KP;
        unsigned a0 = *(const unsigned*)xr0;
        unsigned a1 = *(const unsigned*)xr1;
        unsigned a2 = *(const unsigned*)(xr0 + 8);
        unsigned a3 = *(const unsigned*)(xr1 + 8);
        unsigned bfr[2][2];
#pragma unroll
        for (int nt = 0; nt < 2; nt++) {
            int n = warpN * 16 + nt * 8 + gid;
            const __nv_bfloat16* wp = ws + n * KP + k0 + 2 * tig;
            bfr[nt][0] = *(const unsigned*)wp;
            bfr[nt][1] = *(const unsigned*)(wp + 8);
        }
#pragma unroll
        for (int nt = 0; nt < 2; nt++)
            asm volatile(
                "mma.sync.aligned.m16n8k16.row.col.f32.bf16.bf16.f32 "
                "{%0,%1,%2,%3}, {%4,%5,%6,%7}, {%8,%9}, {%0,%1,%2,%3};\n"
                : "+f"(acc[nt][0]), "+f"(acc[nt][1]),
                  "+f"(acc[nt][2]), "+f"(acc[nt][3])
                : "r"(a0), "r"(a1), "r"(a2), "r"(a3),
                  "r"(bfr[nt][0]), "r"(bfr[nt][1]));
    }
}

#define GEMM_SMEM ((128 + 16) * KP * (int)sizeof(__nv_bfloat16))   // 39168 B

// ================= lin GEMM (M=16): y = fp8(relu(x @ W + b)) =================
__global__ void __launch_bounds__(256) gemm_lin(
    const float* __restrict__ A, int wtoff, const float* __restrict__ Bv,
    float* __restrict__ Y)
{
    extern __shared__ __nv_bfloat16 smb[];
    __nv_bfloat16* ws = smb;
    __nv_bfloat16* xs = smb + 128 * KP;
    __shared__ float bs[128];

    const int tid  = threadIdx.x;
    const int row0 = blockIdx.x * 16;
    if (tid < 128) bs[tid] = Bv[tid];

    const int lane = tid & 31, wid = tid >> 5;
    const int gid = lane >> 2, tig = lane & 3;

    float acc[2][4];
#pragma unroll
    for (int nt = 0; nt < 2; nt++)
#pragma unroll
        for (int i = 0; i < 4; i++) acc[nt][i] = 0.f;

    stage_w(ws, g_wt + wtoff, tid);
    stage_x16(xs, A, row0, tid);
    __syncthreads();
    mma_tile16(ws, xs, wid, gid, tig, acc);

#pragma unroll
    for (int nt = 0; nt < 2; nt++) {
        int col = wid * 16 + nt * 8 + 2 * tig;
        float b0 = bs[col], b1 = bs[col + 1];
        float v0 = fmaxf(acc[nt][0] + b0, 0.f), v1 = fmaxf(acc[nt][1] + b1, 0.f);
        float v2 = fmaxf(acc[nt][2] + b0, 0.f), v3 = fmaxf(acc[nt][3] + b1, 0.f);
        int row = row0 + gid;
        if (row < NN) ((unsigned short*)Y)[row * 64 + (col >> 1)] = pack_e4m3x2(v0, v1);
        if (row + 8 < NN) ((unsigned short*)Y)[(row + 8) * 64 + (col >> 1)] = pack_e4m3x2(v2, v3);
    }
}

// ================= concat GEMM (M=16, two-pass channels) + L2norm =================
__global__ void __launch_bounds__(256) gemm_cat(
    const float* __restrict__ A, const float* __restrict__ A2,
    int wtoff, const float* __restrict__ Bv,
    float* __restrict__ Y)
{
    extern __shared__ __nv_bfloat16 smb[];
    __nv_bfloat16* ws = smb;
    __nv_bfloat16* xs = smb + 128 * KP;
    __shared__ float bs[128];

    const int tid  = threadIdx.x;
    const int row0 = blockIdx.x * 16;
    if (tid < 128) bs[tid] = Bv[tid];

    const int lane = tid & 31, wid = tid >> 5;
    const int gid = lane >> 2, tig = lane & 3;

    float acc[2][4];
#pragma unroll
    for (int nt = 0; nt < 2; nt++)
#pragma unroll
        for (int i = 0; i < 4; i++) acc[nt][i] = 0.f;

    for (int ch = 0; ch < 2; ch++) {
        if (ch) __syncthreads();
        stage_w(ws, g_wt + wtoff + ch * 16384, tid);
        stage_x16(xs, ch == 0 ? A : A2, row0, tid);
        __syncthreads();
        mma_tile16(ws, xs, wid, gid, tig, acc);
    }

    // bias + relu into fp32 smem (16 x 132), then row-L2-normalize
    float* xf = (float*)smb;
    __syncthreads();
#pragma unroll
    for (int nt = 0; nt < 2; nt++) {
        int col = wid * 16 + nt * 8 + 2 * tig;
        float b0 = bs[col], b1 = bs[col + 1];
        xf[gid * 132 + col]           = fmaxf(acc[nt][0] + b0, 0.f);
        xf[gid * 132 + col + 1]       = fmaxf(acc[nt][1] + b1, 0.f);
        xf[(gid + 8) * 132 + col]     = fmaxf(acc[nt][2] + b0, 0.f);
        xf[(gid + 8) * 132 + col + 1] = fmaxf(acc[nt][3] + b1, 0.f);
    }
    __syncthreads();
    // 16 threads per row, 8 cols (2 float4) each
    int r = tid >> 4, q = tid & 15;
    const float4* rowp = (const float4*)(xf + r * 132) + q * 2;
    float4 v0 = rowp[0], v1 = rowp[1];
    float s = v0.x * v0.x + v0.y * v0.y + v0.z * v0.z + v0.w * v0.w
            + v1.x * v1.x + v1.y * v1.y + v1.z * v1.z + v1.w * v1.w;
    s += __shfl_xor_sync(0xffffffffu, s, 1);
    s += __shfl_xor_sync(0xffffffffu, s, 2);
    s += __shfl_xor_sync(0xffffffffu, s, 4);
    s += __shfl_xor_sync(0xffffffffu, s, 8);
    float inv = 1.f / fmaxf(sqrtf(s), 1e-12f);
    int row = row0 + r;
    if (row < NN) {
        float4* dst = (float4*)(Y + row * 128) + q * 2;
        v0.x *= inv; v0.y *= inv; v0.z *= inv; v0.w *= inv;
        v1.x *= inv; v1.y *= inv; v1.z *= inv; v1.w *= inv;
        dst[0] = v0; dst[1] = v1;
    }
}

// ---------------- scatter-mean: warp per dst node, unroll-8, f16x2 SIMD ----------------
__global__ void __launch_bounds__(256) agg_k(const float* __restrict__ Ys,
                                             float* __restrict__ Ag)
{
    int w = (blockIdx.x * blockDim.x + threadIdx.x) >> 5;
    int lane = threadIdx.x & 31;
    if (w >= NN) return;
    int cnt = g_fill[w];
    int n = cnt < BUCKET ? cnt : BUCKET;
    const int* col = g_colb + w * BUCKET;
    const unsigned* Yb = (const unsigned*)Ys;

    __half2 z = __float2half2_rn(0.f);
    __half2 ca[8] = {z, z, z, z, z, z, z, z};
    __half2 cb[8] = {z, z, z, z, z, z, z, z};
    int e = 0;
    for (; e + 8 <= n; e += 8) {
        int4 i0 = *(const int4*)(col + e);
        int4 i1 = *(const int4*)(col + e + 4);
        unsigned v[8];
        v[0] = Yb[i0.x * 32 + lane]; v[1] = Yb[i0.y * 32 + lane];
        v[2] = Yb[i0.z * 32 + lane]; v[3] = Yb[i0.w * 32 + lane];
        v[4] = Yb[i1.x * 32 + lane]; v[5] = Yb[i1.y * 32 + lane];
        v[6] = Yb[i1.z * 32 + lane]; v[7] = Yb[i1.w * 32 + lane];
#pragma unroll
        for (int i = 0; i < 8; i++) {
            unsigned p0, p1;
            e4m3x4_to_h2(v[i], p0, p1);
            ca[i] = __hadd2(ca[i], *(__half2*)&p0);
            cb[i] = __hadd2(cb[i], *(__half2*)&p1);
        }
    }
    for (; e < n; e++) {
        unsigned v0 = Yb[col[e] * 32 + lane];
        unsigned p0, p1;
        e4m3x4_to_h2(v0, p0, p1);
        ca[0] = __hadd2(ca[0], *(__half2*)&p0);
        cb[0] = __hadd2(cb[0], *(__half2*)&p1);
    }
    // pairwise tree combine (f16), then fp32 finish
    ca[0] = __hadd2(ca[0], ca[1]); ca[2] = __hadd2(ca[2], ca[3]);
    ca[4] = __hadd2(ca[4], ca[5]); ca[6] = __hadd2(ca[6], ca[7]);
    cb[0] = __hadd2(cb[0], cb[1]); cb[2] = __hadd2(cb[2], cb[3]);
    cb[4] = __hadd2(cb[4], cb[5]); cb[6] = __hadd2(cb[6], cb[7]);
    float2 a0 = __half22float2(ca[0]), a1 = __half22float2(ca[2]);
    float2 a2 = __half22float2(ca[4]), a3 = __half22float2(ca[6]);
    float2 b0 = __half22float2(cb[0]), b1 = __half22float2(cb[2]);
    float2 b2 = __half22float2(cb[4]), b3 = __half22float2(cb[6]);
    float inv = 1.f / (float)(cnt > 0 ? cnt : 1);
    float4 o;
    o.x = ((a0.x + a1.x) + (a2.x + a3.x)) * inv;
    o.y = ((a0.y + a1.y) + (a2.y + a3.y)) * inv;
    o.z = ((b0.x + b1.x) + (b2.x + b3.x)) * inv;
    o.w = ((b0.y + b1.y) + (b2.y + b3.y)) * inv;
    ((float4*)Ag)[w * 32 + lane] = o;
}

// ---------------- fused (combined mp) + log_softmax ----------------
__global__ void __launch_bounds__(256) post_k(const float* __restrict__ T,
                                              float* __restrict__ Out)
{
    __shared__ float w2s[128 * 64];
    __shared__ float b2s[64];
    __shared__ float ts[4][128];
    __shared__ float zs[4][64];

    int tid = threadIdx.x;
    for (int i = tid; i < 128 * 64; i += 256) w2s[i] = g_wc[i];
    if (tid < 64) b2s[tid] = g_bc[tid];

    int g = tid >> 6;
    int c = tid & 63;

    for (int n0 = blockIdx.x * 4; n0 < NN; n0 += gridDim.x * 4) {
        int node = n0 + g;
        __syncthreads();
        if (node < NN) {
            ts[g][c]      = T[node * 128 + c];
            ts[g][c + 64] = T[node * 128 + c + 64];
        }
        __syncthreads();

        float z = b2s[c];
        if (node < NN) {
#pragma unroll 8
            for (int k = 0; k < 128; k++)
                z += ts[g][k] * w2s[k * 64 + c];
        }
        zs[g][c] = z;
        __syncthreads();

        float other = zs[g][c ^ 32];
        float pm = fmaxf(z, other);
#pragma unroll
        for (int off = 16; off; off >>= 1)
            pm = fmaxf(pm, __shfl_xor_sync(0xffffffffu, pm, off));
        float ps = expf(z - pm) + expf(other - pm);
#pragma unroll
        for (int off = 16; off; off >>= 1)
            ps += __shfl_xor_sync(0xffffffffu, ps, off);
        float lse = pm + logf(ps);

        if (node < NN) Out[node * 64 + c] = z - lse;
    }
}

// ---------------- launch ----------------
extern "C" void kernel_launch(void* const* d_in, const int* in_sizes, int n_in,
                              void* d_out, int out_size)
{
    const float* x      = (const float*)d_in[0];
    const void*  ei     = d_in[1];
    const float* lin_w0 = (const float*)d_in[2];
    const float* lin_b0 = (const float*)d_in[3];
    const float* agg_w0 = (const float*)d_in[4];
    const float* agg_b0 = (const float*)d_in[5];
    const float* lin_w1 = (const float*)d_in[6];
    const float* lin_b1 = (const float*)d_in[7];
    const float* agg_w1 = (const float*)d_in[8];
    const float* agg_b1 = (const float*)d_in[9];
    const float* mp_w1  = (const float*)d_in[10];
    const float* mp_b1  = (const float*)d_in[11];
    const float* mp_w2  = (const float*)d_in[12];
    const float* mp_b2  = (const float*)d_in[13];
    float* out = (float*)d_out;

    float *p_y, *p_aggr, *p_h0, *p_h1;
    int* p_fill;
    cudaGetSymbolAddress((void**)&p_y,    g_y);
    cudaGetSymbolAddress((void**)&p_aggr, g_aggr);
    cudaGetSymbolAddress((void**)&p_h0,   g_h0);
    cudaGetSymbolAddress((void**)&p_h1,   g_h1);
    cudaGetSymbolAddress((void**)&p_fill, g_fill);

    // one-time host-side resources (no device memory)
    static cudaStream_t s2 = nullptr;
    static cudaEvent_t evFork = nullptr, evJoin = nullptr;
    if (s2 == nullptr) {
        cudaStreamCreateWithFlags(&s2, cudaStreamNonBlocking);
        cudaEventCreateWithFlags(&evFork, cudaEventDisableTiming);
        cudaEventCreateWithFlags(&evJoin, cudaEventDisableTiming);
    }

    cudaFuncSetAttribute(gemm_lin, cudaFuncAttributeMaxDynamicSharedMemorySize, GEMM_SMEM);
    cudaFuncSetAttribute(gemm_cat, cudaFuncAttributeMaxDynamicSharedMemorySize, GEMM_SMEM);

    const int GEMM_GRID = (NN + 15) / 16;        // 625
    const int AGG_GRID  = (NN * 32 + 255) / 256; // 1250
    const int FILL_GRID = 313;                   // 8 edges/thread

    // fork: adjacency build on s2; weight prep + lin0 on main stream
    cudaEventRecord(evFork, 0);
    cudaStreamWaitEvent(s2, evFork, 0);
    cudaMemsetAsync(p_fill, 0, NN * sizeof(int), s2);
    fill_k<<<FILL_GRID, 256, 0, s2>>>(ei);
    cudaEventRecord(evJoin, s2);

    prep_k<<<128, 256>>>(lin_w0, agg_w0, lin_w1, agg_w1, mp_w1, mp_b1, mp_w2, mp_b2);
    gemm_lin<<<GEMM_GRID, 256, GEMM_SMEM>>>(x, 0, lin_b0, p_y);

    // join: agg0 needs message table (main) + adjacency (s2)
    cudaStreamWaitEvent(0, evJoin, 0);
    agg_k<<<AGG_GRID, 256>>>(p_y, p_aggr);
    gemm_cat<<<GEMM_GRID, 256, GEMM_SMEM>>>(x, p_aggr, 16384, agg_b0, p_h0);

    // layer 1
    gemm_lin<<<GEMM_GRID, 256, GEMM_SMEM>>>(p_h0, 49152, lin_b1, p_y);
    agg_k<<<AGG_GRID, 256>>>(p_y, p_aggr);
    gemm_cat<<<GEMM_GRID, 256, GEMM_SMEM>>>(p_h0, p_aggr, 65536, agg_b1, p_h1);

    // fused post-MLP + log_softmax
    post_k<<<640, 256>>>(p_h1, out);
}

// round 14
// speedup vs baseline: 1.0402x; 1.0402x over previous
#include <cuda_runtime.h>
#include <cuda_bf16.h>
#include <cuda_fp16.h>
#include <math.h>

#define NN 10000
#define EE 640000
#define DD 128
#define BUCKET 192
#define KP 136   // padded k stride (bf16 elems)

// ---------------- device scratch ----------------
__device__ float g_y[NN * DD];        // fp8-packed message table
__device__ float g_aggr[NN * DD];     // bf16-packed aggregate (row = 128 bf16 = 32 uint2)
__device__ float g_h0[NN * DD];
__device__ float g_h1[NN * DD];
__device__ int   g_fill[NN];
__device__ int   g_colb[NN * BUCKET];
// transposed bf16 weights: lin0 @0 | agg0 ch0 @16384 ch1 @32768 | lin1 @49152 | agg1 ch0 @65536 ch1 @81920
__device__ __nv_bfloat16 g_wt[16384 * 6];
__device__ float g_wc[128 * 64];      // combined mp_w1 @ mp_w2
__device__ float g_bc[64];            // combined mp_b1 @ mp_w2 + mp_b2

// ---------------- adjacency fill: 8 edges/thread (embedded dtype sniff) ----------------
__global__ void __launch_bounds__(256) fill_k(const void* __restrict__ ei) {
    __shared__ int s64;
    if (threadIdx.x == 0) {
        const int* w = (const int*)ei;
        int ornz = 0;
#pragma unroll
        for (int j = 1; j < 64; j += 2) ornz |= w[j];
        s64 = (ornz == 0);
    }
    __syncthreads();
    int base0 = (blockIdx.x * 256 + threadIdx.x) * 8;
#pragma unroll
    for (int half = 0; half < 2; half++) {
        int base = base0 + half * 4;
        if (base >= EE) break;
        int d[4], s[4];
        if (s64) {
            const longlong2* pd = (const longlong2*)((const long long*)ei + EE + base);
            const longlong2* ps = (const longlong2*)((const long long*)ei + base);
            longlong2 q0 = pd[0], q1 = pd[1];
            longlong2 r0 = ps[0], r1 = ps[1];
            d[0] = (int)q0.x; d[1] = (int)q0.y; d[2] = (int)q1.x; d[3] = (int)q1.y;
            s[0] = (int)r0.x; s[1] = (int)r0.y; s[2] = (int)r1.x; s[3] = (int)r1.y;
        } else {
            int4 q = *(const int4*)((const int*)ei + EE + base);
            int4 r = *(const int4*)((const int*)ei + base);
            d[0] = q.x; d[1] = q.y; d[2] = q.z; d[3] = q.w;
            s[0] = r.x; s[1] = r.y; s[2] = r.z; s[3] = r.w;
        }
#pragma unroll
        for (int i = 0; i < 4; i++) {
            int pos = atomicAdd(&g_fill[d[i]], 1);
            if (pos < BUCKET) g_colb[d[i] * BUCKET + pos] = s[i];
        }
    }
}

// ---------------- weight prep ----------------
__global__ void __launch_bounds__(256) prep_k(
    const float* __restrict__ w0, const float* __restrict__ aw0,
    const float* __restrict__ w1, const float* __restrict__ aw1,
    const float* __restrict__ mw1, const float* __restrict__ mb1,
    const float* __restrict__ mw2, const float* __restrict__ mb2)
{
    int idx = blockIdx.x * 256 + threadIdx.x;   // 0..32767
    if (idx < 24576) {
        const float* src; int dstb, f;
        if (idx < 4096)       { src = w0;  dstb = 0;     f = idx; }
        else if (idx < 12288) { src = aw0; dstb = 16384; f = idx - 4096; }
        else if (idx < 16384) { src = w1;  dstb = 49152; f = idx - 12288; }
        else                  { src = aw1; dstb = 65536; f = idx - 16384; }
        float4 v = ((const float4*)src)[f];
        int k  = f >> 5;
        int n0 = (f & 31) * 4;
        int ch = k >> 7, kk = k & 127;
        __nv_bfloat16* dst = g_wt + dstb + ch * 16384 + kk;
        dst[(n0 + 0) * 128] = __float2bfloat16_rn(v.x);
        dst[(n0 + 1) * 128] = __float2bfloat16_rn(v.y);
        dst[(n0 + 2) * 128] = __float2bfloat16_rn(v.z);
        dst[(n0 + 3) * 128] = __float2bfloat16_rn(v.w);
    } else {
        int j = idx - 24576;                // 0..8191
        int m = j >> 6, n = j & 63;
        float s = 0.f;
#pragma unroll 8
        for (int k = 0; k < 128; k++)
            s += mw1[m * 128 + k] * mw2[k * 64 + n];
        g_wc[j] = s;
        if (j < 64) {
            float t = mb2[j];
#pragma unroll 8
            for (int k = 0; k < 128; k++)
                t += mb1[k] * mw2[k * 64 + j];
            g_bc[j] = t;
        }
    }
}

// ---------------- fp8 helpers ----------------
__device__ __forceinline__ unsigned short pack_e4m3x2(float v0, float v1) {
    unsigned short r;
    asm("cvt.rn.satfinite.e4m3x2.f32 %0, %2, %1;" : "=h"(r) : "f"(v0), "f"(v1));
    return r;
}
__device__ __forceinline__ void e4m3x4_to_h2(unsigned v, unsigned& h01, unsigned& h23) {
    asm("{ .reg .b16 lo, hi;\n\t"
        "mov.b32 {lo, hi}, %2;\n\t"
        "cvt.rn.f16x2.e4m3x2 %0, lo;\n\t"
        "cvt.rn.f16x2.e4m3x2 %1, hi; }"
        : "=r"(h01), "=r"(h23) : "r"(v));
}

// ---------------- shared GEMM building blocks (M=32 tiles) ----------------
__device__ __forceinline__ void stage_w(__nv_bfloat16* ws, const __nv_bfloat16* Wsrc, int tid) {
    const uint4* Wg = (const uint4*)Wsrc;
#pragma unroll
    for (int it = 0; it < 8; it++) {
        int idx = tid + it * 256;
        int n = idx >> 4, k8 = idx & 15;
        *(uint4*)(ws + n * KP + k8 * 8) = Wg[idx];
    }
}
__device__ __forceinline__ void stage_x(__nv_bfloat16* xs, const float* Asrc, int row0, int tid) {
#pragma unroll
    for (int it = 0; it < 4; it++) {
        int idx = tid + it * 256;
        int r = idx >> 5, c4 = idx & 31;
        int row = row0 + r;
        float4 v = make_float4(0.f, 0.f, 0.f, 0.f);
        if (row < NN) v = ((const float4*)Asrc)[row * 32 + c4];
        __nv_bfloat162 p0 = __floats2bfloat162_rn(v.x, v.y);
        __nv_bfloat162 p1 = __floats2bfloat162_rn(v.z, v.w);
        *(uint2*)(xs + r * KP + c4 * 4) = make_uint2(*(unsigned*)&p0, *(unsigned*)&p1);
    }
}
// bf16 source variant (aggr): pure copy, no cvt
__device__ __forceinline__ void stage_x_bf16(__nv_bfloat16* xs, const float* Asrc, int row0, int tid) {
#pragma unroll
    for (int it = 0; it < 4; it++) {
        int idx = tid + it * 256;
        int r = idx >> 5, c4 = idx & 31;
        int row = row0 + r;
        uint2 v = make_uint2(0u, 0u);
        if (row < NN) v = ((const uint2*)Asrc)[row * 32 + c4];
        *(uint2*)(xs + r * KP + c4 * 4) = v;
    }
}
__device__ __forceinline__ void mma_tile(const __nv_bfloat16* ws, const __nv_bfloat16* xs,
                                         int warpM, int warpN, int gid, int tig,
                                         float acc[4][4]) {
#pragma unroll
    for (int ks = 0; ks < 8; ks++) {
        const int k0 = ks * 16;
        int r = warpM * 16 + gid;
        const __nv_bfloat16* xr0 = xs + r * KP + k0 + 2 * tig;
        const __nv_bfloat16* xr1 = xr0 + 8 * KP;
        unsigned a0 = *(const unsigned*)xr0;
        unsigned a1 = *(const unsigned*)xr1;
        unsigned a2 = *(const unsigned*)(xr0 + 8);
        unsigned a3 = *(const unsigned*)(xr1 + 8);
        unsigned bfr[4][2];
#pragma unroll
        for (int nt = 0; nt < 4; nt++) {
            int n = warpN * 32 + nt * 8 + gid;
            const __nv_bfloat16* wp = ws + n * KP + k0 + 2 * tig;
            bfr[nt][0] = *(const unsigned*)wp;
            bfr[nt][1] = *(const unsigned*)(wp + 8);
        }
#pragma unroll
        for (int nt = 0; nt < 4; nt++)
            asm volatile(
                "mma.sync.aligned.m16n8k16.row.col.f32.bf16.bf16.f32 "
                "{%0,%1,%2,%3}, {%4,%5,%6,%7}, {%8,%9}, {%0,%1,%2,%3};\n"
                : "+f"(acc[nt][0]), "+f"(acc[nt][1]),
                  "+f"(acc[nt][2]), "+f"(acc[nt][3])
                : "r"(a0), "r"(a1), "r"(a2), "r"(a3),
                  "r"(bfr[nt][0]), "r"(bfr[nt][1]));
    }
}

#define GEMM_SMEM ((128 + 32) * KP * (int)sizeof(__nv_bfloat16))   // 43520 B

// ================= lin GEMM: y = fp8(relu(x @ W + b)) =================
__global__ void __launch_bounds__(256) gemm_lin(
    const float* __restrict__ A, int wtoff, const float* __restrict__ Bv,
    float* __restrict__ Y)
{
    extern __shared__ __nv_bfloat16 smb[];
    __nv_bfloat16* ws = smb;
    __nv_bfloat16* xs = smb + 128 * KP;
    __shared__ float bs[128];

    const int tid  = threadIdx.x;
    const int row0 = blockIdx.x * 32;
    if (tid < 128) bs[tid] = Bv[tid];

    const int lane = tid & 31, wid = tid >> 5;
    const int gid = lane >> 2, tig = lane & 3;
    const int warpM = wid >> 2, warpN = wid & 3;

    float acc[4][4];
#pragma unroll
    for (int nt = 0; nt < 4; nt++)
#pragma unroll
        for (int i = 0; i < 4; i++) acc[nt][i] = 0.f;

    stage_w(ws, g_wt + wtoff, tid);
    stage_x(xs, A, row0, tid);
    __syncthreads();
    mma_tile(ws, xs, warpM, warpN, gid, tig, acc);

    int rl = warpM * 16 + gid;
#pragma unroll
    for (int nt = 0; nt < 4; nt++) {
        int col = warpN * 32 + nt * 8 + 2 * tig;
        float b0 = bs[col], b1 = bs[col + 1];
        float v0 = fmaxf(acc[nt][0] + b0, 0.f), v1 = fmaxf(acc[nt][1] + b1, 0.f);
        float v2 = fmaxf(acc[nt][2] + b0, 0.f), v3 = fmaxf(acc[nt][3] + b1, 0.f);
        int row = row0 + rl;
        if (row < NN) ((unsigned short*)Y)[row * 64 + (col >> 1)] = pack_e4m3x2(v0, v1);
        if (row + 8 < NN) ((unsigned short*)Y)[(row + 8) * 64 + (col >> 1)] = pack_e4m3x2(v2, v3);
    }
}

// ================= concat GEMM (two-pass; ch0 fp32 src, ch1 bf16 aggr) + L2norm =================
__global__ void __launch_bounds__(256) gemm_cat(
    const float* __restrict__ A, const float* __restrict__ A2,
    int wtoff, const float* __restrict__ Bv,
    float* __restrict__ Y)
{
    extern __shared__ __nv_bfloat16 smb[];
    __nv_bfloat16* ws = smb;
    __nv_bfloat16* xs = smb + 128 * KP;
    __shared__ float bs[128];

    const int tid  = threadIdx.x;
    const int row0 = blockIdx.x * 32;
    if (tid < 128) bs[tid] = Bv[tid];

    const int lane = tid & 31, wid = tid >> 5;
    const int gid = lane >> 2, tig = lane & 3;
    const int warpM = wid >> 2, warpN = wid & 3;

    float acc[4][4];
#pragma unroll
    for (int nt = 0; nt < 4; nt++)
#pragma unroll
        for (int i = 0; i < 4; i++) acc[nt][i] = 0.f;

    for (int ch = 0; ch < 2; ch++) {
        if (ch) __syncthreads();
        stage_w(ws, g_wt + wtoff + ch * 16384, tid);
        if (ch == 0) stage_x(xs, A, row0, tid);
        else         stage_x_bf16(xs, A2, row0, tid);
        __syncthreads();
        mma_tile(ws, xs, warpM, warpN, gid, tig, acc);
    }

    // bias + relu into fp32 smem, then row-L2-normalize
    float* xf = (float*)smb;
    __syncthreads();
    int rl = warpM * 16 + gid;
#pragma unroll
    for (int nt = 0; nt < 4; nt++) {
        int col = warpN * 32 + nt * 8 + 2 * tig;
        float b0 = bs[col], b1 = bs[col + 1];
        xf[rl * 132 + col]           = fmaxf(acc[nt][0] + b0, 0.f);
        xf[rl * 132 + col + 1]       = fmaxf(acc[nt][1] + b1, 0.f);
        xf[(rl + 8) * 132 + col]     = fmaxf(acc[nt][2] + b0, 0.f);
        xf[(rl + 8) * 132 + col + 1] = fmaxf(acc[nt][3] + b1, 0.f);
    }
    __syncthreads();
    int r = tid >> 3, q = tid & 7;
    const float4* rowp = (const float4*)(xf + r * 132) + q * 4;
    float4 vv[4];
    float s = 0.f;
#pragma unroll
    for (int i = 0; i < 4; i++) {
        vv[i] = rowp[i];
        s += vv[i].x * vv[i].x + vv[i].y * vv[i].y + vv[i].z * vv[i].z + vv[i].w * vv[i].w;
    }
    s += __shfl_xor_sync(0xffffffffu, s, 1);
    s += __shfl_xor_sync(0xffffffffu, s, 2);
    s += __shfl_xor_sync(0xffffffffu, s, 4);
    float inv = 1.f / fmaxf(sqrtf(s), 1e-12f);
    int row = row0 + r;
    if (row < NN) {
        float4* dst = (float4*)(Y + row * 128) + q * 4;
#pragma unroll
        for (int i = 0; i < 4; i++) {
            float4 o = vv[i];
            o.x *= inv; o.y *= inv; o.z *= inv; o.w *= inv;
            dst[i] = o;
        }
    }
}

// ---------------- scatter-mean: warp per dst, unroll-4 + index prefetch, bf16 out ----------------
__global__ void __launch_bounds__(256) agg_k(const float* __restrict__ Ys,
                                             float* __restrict__ Ag)
{
    int w = (blockIdx.x * blockDim.x + threadIdx.x) >> 5;
    int lane = threadIdx.x & 31;
    if (w >= NN) return;
    int cnt = g_fill[w];
    int n = cnt < BUCKET ? cnt : BUCKET;
    const int* col = g_colb + w * BUCKET;
    const unsigned* Yb = (const unsigned*)Ys;

    __half2 z = __float2half2_rn(0.f);
    __half2 c0a = z, c0b = z, c1a = z, c1b = z;
    __half2 c2a = z, c2b = z, c3a = z, c3b = z;
    int e = 0;
    int4 idx = make_int4(0, 0, 0, 0);
    if (n >= 4) idx = *(const int4*)col;
    for (; e + 4 <= n; e += 4) {
        int4 cur = idx;
        if (e + 8 <= n) idx = *(const int4*)(col + e + 4);   // prefetch next indices
        unsigned v0 = Yb[cur.x * 32 + lane];
        unsigned v1 = Yb[cur.y * 32 + lane];
        unsigned v2 = Yb[cur.z * 32 + lane];
        unsigned v3 = Yb[cur.w * 32 + lane];
        unsigned p0, p1, q0, q1, r0, r1, t0, t1;
        e4m3x4_to_h2(v0, p0, p1);
        e4m3x4_to_h2(v1, q0, q1);
        e4m3x4_to_h2(v2, r0, r1);
        e4m3x4_to_h2(v3, t0, t1);
        c0a = __hadd2(c0a, *(__half2*)&p0);  c0b = __hadd2(c0b, *(__half2*)&p1);
        c1a = __hadd2(c1a, *(__half2*)&q0);  c1b = __hadd2(c1b, *(__half2*)&q1);
        c2a = __hadd2(c2a, *(__half2*)&r0);  c2b = __hadd2(c2b, *(__half2*)&r1);
        c3a = __hadd2(c3a, *(__half2*)&t0);  c3b = __hadd2(c3b, *(__half2*)&t1);
    }
    for (; e < n; e++) {
        unsigned v0 = Yb[col[e] * 32 + lane];
        unsigned p0, p1;
        e4m3x4_to_h2(v0, p0, p1);
        c0a = __hadd2(c0a, *(__half2*)&p0);
        c0b = __hadd2(c0b, *(__half2*)&p1);
    }
    float2 a0 = __half22float2(c0a), a1 = __half22float2(c1a);
    float2 a2 = __half22float2(c2a), a3 = __half22float2(c3a);
    float2 b0 = __half22float2(c0b), b1 = __half22float2(c1b);
    float2 b2 = __half22float2(c2b), b3 = __half22float2(c3b);
    float inv = 1.f / (float)(cnt > 0 ? cnt : 1);
    float ox = ((a0.x + a1.x) + (a2.x + a3.x)) * inv;
    float oy = ((a0.y + a1.y) + (a2.y + a3.y)) * inv;
    float oz = ((b0.x + b1.x) + (b2.x + b3.x)) * inv;
    float ow = ((b0.y + b1.y) + (b2.y + b3.y)) * inv;
    __nv_bfloat162 w0 = __floats2bfloat162_rn(ox, oy);
    __nv_bfloat162 w1 = __floats2bfloat162_rn(oz, ow);
    ((uint2*)Ag)[w * 32 + lane] = make_uint2(*(unsigned*)&w0, *(unsigned*)&w1);
}

// ---------------- fused (combined mp) + log_softmax ----------------
__global__ void __launch_bounds__(256) post_k(const float* __restrict__ T,
                                              float* __restrict__ Out)
{
    __shared__ float w2s[128 * 64];
    __shared__ float b2s[64];
    __shared__ float ts[4][128];
    __shared__ float zs[4][64];

    int tid = threadIdx.x;
    for (int i = tid; i < 128 * 64; i += 256) w2s[i] = g_wc[i];
    if (tid < 64) b2s[tid] = g_bc[tid];

    int g = tid >> 6;
    int c = tid & 63;

    for (int n0 = blockIdx.x * 4; n0 < NN; n0 += gridDim.x * 4) {
        int node = n0 + g;
        __syncthreads();
        if (node < NN) {
            ts[g][c]      = T[node * 128 + c];
            ts[g][c + 64] = T[node * 128 + c + 64];
        }
        __syncthreads();

        float z = b2s[c];
        if (node < NN) {
#pragma unroll 8
            for (int k = 0; k < 128; k++)
                z += ts[g][k] * w2s[k * 64 + c];
        }
        zs[g][c] = z;
        __syncthreads();

        float other = zs[g][c ^ 32];
        float pm = fmaxf(z, other);
#pragma unroll
        for (int off = 16; off; off >>= 1)
            pm = fmaxf(pm, __shfl_xor_sync(0xffffffffu, pm, off));
        float ps = expf(z - pm) + expf(other - pm);
#pragma unroll
        for (int off = 16; off; off >>= 1)
            ps += __shfl_xor_sync(0xffffffffu, ps, off);
        float lse = pm + logf(ps);

        if (node < NN) Out[node * 64 + c] = z - lse;
    }
}

// ---------------- launch ----------------
extern "C" void kernel_launch(void* const* d_in, const int* in_sizes, int n_in,
                              void* d_out, int out_size)
{
    const float* x      = (const float*)d_in[0];
    const void*  ei     = d_in[1];
    const float* lin_w0 = (const float*)d_in[2];
    const float* lin_b0 = (const float*)d_in[3];
    const float* agg_w0 = (const float*)d_in[4];
    const float* agg_b0 = (const float*)d_in[5];
    const float* lin_w1 = (const float*)d_in[6];
    const float* lin_b1 = (const float*)d_in[7];
    const float* agg_w1 = (const float*)d_in[8];
    const float* agg_b1 = (const float*)d_in[9];
    const float* mp_w1  = (const float*)d_in[10];
    const float* mp_b1  = (const float*)d_in[11];
    const float* mp_w2  = (const float*)d_in[12];
    const float* mp_b2  = (const float*)d_in[13];
    float* out = (float*)d_out;

    float *p_y, *p_aggr, *p_h0, *p_h1;
    int* p_fill;
    cudaGetSymbolAddress((void**)&p_y,    g_y);
    cudaGetSymbolAddress((void**)&p_aggr, g_aggr);
    cudaGetSymbolAddress((void**)&p_h0,   g_h0);
    cudaGetSymbolAddress((void**)&p_h1,   g_h1);
    cudaGetSymbolAddress((void**)&p_fill, g_fill);

    // one-time host-side resources (no device memory)
    static cudaStream_t s2 = nullptr;
    static cudaEvent_t evFork = nullptr, evJoin = nullptr;
    if (s2 == nullptr) {
        cudaStreamCreateWithFlags(&s2, cudaStreamNonBlocking);
        cudaEventCreateWithFlags(&evFork, cudaEventDisableTiming);
        cudaEventCreateWithFlags(&evJoin, cudaEventDisableTiming);
    }

    cudaFuncSetAttribute(gemm_lin, cudaFuncAttributeMaxDynamicSharedMemorySize, GEMM_SMEM);
    cudaFuncSetAttribute(gemm_cat, cudaFuncAttributeMaxDynamicSharedMemorySize, GEMM_SMEM);

    const int GEMM_GRID = (NN + 31) / 32;        // 313
    const int AGG_GRID  = (NN * 32 + 255) / 256; // 1250
    const int FILL_GRID = 313;                   // 8 edges/thread

    // fork: adjacency build on s2; weight prep + lin0 on main stream
    cudaEventRecord(evFork, 0);
    cudaStreamWaitEvent(s2, evFork, 0);
    cudaMemsetAsync(p_fill, 0, NN * sizeof(int), s2);
    fill_k<<<FILL_GRID, 256, 0, s2>>>(ei);
    cudaEventRecord(evJoin, s2);

    prep_k<<<128, 256>>>(lin_w0, agg_w0, lin_w1, agg_w1, mp_w1, mp_b1, mp_w2, mp_b2);
    gemm_lin<<<GEMM_GRID, 256, GEMM_SMEM>>>(x, 0, lin_b0, p_y);

    // join: agg0 needs message table (main) + adjacency (s2)
    cudaStreamWaitEvent(0, evJoin, 0);
    agg_k<<<AGG_GRID, 256>>>(p_y, p_aggr);
    gemm_cat<<<GEMM_GRID, 256, GEMM_SMEM>>>(x, p_aggr, 16384, agg_b0, p_h0);

    // layer 1
    gemm_lin<<<GEMM_GRID, 256, GEMM_SMEM>>>(p_h0, 49152, lin_b1, p_y);
    agg_k<<<AGG_GRID, 256>>>(p_y, p_aggr);
    gemm_cat<<<GEMM_GRID, 256, GEMM_SMEM>>>(p_h0, p_aggr, 65536, agg_b1, p_h1);

    // fused post-MLP + log_softmax
    post_k<<<640, 256>>>(p_h1, out);
}